// round 14
// baseline (speedup 1.0000x reference)
#include <cuda_runtime.h>
#include <cuda_bf16.h>
#include <cstdint>

// VQ-VAE quantizer — 1-term bf16 HMMA + exact fp32 refinement.
// R14 = R13 resubmitted (previous round died to a broker infra failure).
// Flattened cp.async pipeline (1 sync/slice) + single-pass candidate
// collection against a stale running min (atomicMin on float bits).

#define M_ROWS  65536
#define K_CODES 2048
#define D_DIM   256
#define BM      128
#define BN      128
#define NCHUNK  (K_CODES / BN)   // 16
#define NSLICE  4                // 64-wide k slices
#define NITER   (NCHUNK * NSLICE)
#define NTHREADS 256
#define MAXC    24
#define MARGIN  6e-4f

// smem layout (dynamic)
#define OFF_RUNM  0        // 128 int (float bits)
#define OFF_IDX   512      // 128 int
#define OFF_CNT   1024     // 128 int
#define OFF_WSUM  1536     // 8 float (+pad)
#define OFF_ESQC  2048     // 128 float (current chunk esq slice)
#define OFF_CAND  2560     // 128*24 int = 12288 -> ends 14848
#define OFF_A     15360    // Zh tile 64KB -> ends 80896
#define OFF_B     80896    // 2 x 16KB -> ends 113664
#define SMEM_BYTES 113664  // 2 CTAs/SM incl. per-block reserve

__device__ float  g_zsq[M_ROWS];
__device__ float  g_esq[K_CODES];
__device__ double g_loss;
__device__ __nv_bfloat16 g_Zh[(size_t)M_ROWS * D_DIM];
__device__ __nv_bfloat16 g_Eh[(size_t)K_CODES * D_DIM];

__device__ __forceinline__ uint32_t smem_u32(const void* p) {
    uint32_t a;
    asm("{ .reg .u64 t; cvta.to.shared.u64 t, %1; cvt.u32.u64 %0, t; }" : "=r"(a) : "l"(p));
    return a;
}
__device__ __forceinline__ void ldsm_x4(uint32_t& r0, uint32_t& r1, uint32_t& r2,
                                        uint32_t& r3, uint32_t addr) {
    asm volatile("ldmatrix.sync.aligned.m8n8.x4.shared.b16 {%0,%1,%2,%3}, [%4];"
                 : "=r"(r0), "=r"(r1), "=r"(r2), "=r"(r3) : "r"(addr));
}
__device__ __forceinline__ void ldsm_x2(uint32_t& r0, uint32_t& r1, uint32_t addr) {
    asm volatile("ldmatrix.sync.aligned.m8n8.x2.shared.b16 {%0,%1}, [%2];"
                 : "=r"(r0), "=r"(r1) : "r"(addr));
}
__device__ __forceinline__ void mma16816(float* c, const uint32_t* a, const uint32_t* b) {
    asm volatile("mma.sync.aligned.m16n8k16.row.col.f32.bf16.bf16.f32 "
                 "{%0,%1,%2,%3}, {%4,%5,%6,%7}, {%8,%9}, {%0,%1,%2,%3};"
                 : "+f"(c[0]), "+f"(c[1]), "+f"(c[2]), "+f"(c[3])
                 : "r"(a[0]), "r"(a[1]), "r"(a[2]), "r"(a[3]), "r"(b[0]), "r"(b[1]));
}
__device__ __forceinline__ void cp16(uint32_t dst, const void* src) {
    asm volatile("cp.async.cg.shared.global [%0], [%1], 16;" :: "r"(dst), "l"(src));
}
__device__ __forceinline__ void cp_commit() { asm volatile("cp.async.commit_group;"); }
__device__ __forceinline__ void cp_wait0()  { asm volatile("cp.async.wait_group 0;" ::: "memory"); }

// ---------------- fused prep: convert to bf16 + row sum-of-squares ----------
__global__ void prep_z_kernel(const float* __restrict__ z) {
    int row  = blockIdx.x * 8 + (threadIdx.x >> 5);
    int lane = threadIdx.x & 31;
    const float4* zr = (const float4*)(z + (size_t)row * D_DIM);
    float4 a = zr[lane * 2], b = zr[lane * 2 + 1];
    __nv_bfloat162 p0 = __floats2bfloat162_rn(a.x, a.y);
    __nv_bfloat162 p1 = __floats2bfloat162_rn(a.z, a.w);
    __nv_bfloat162 p2 = __floats2bfloat162_rn(b.x, b.y);
    __nv_bfloat162 p3 = __floats2bfloat162_rn(b.z, b.w);
    uint4 u;
    u.x = *(uint32_t*)&p0; u.y = *(uint32_t*)&p1;
    u.z = *(uint32_t*)&p2; u.w = *(uint32_t*)&p3;
    *(uint4*)(g_Zh + (size_t)row * D_DIM + lane * 8) = u;
    float s = 0.f;
    s = fmaf(a.x, a.x, s); s = fmaf(a.y, a.y, s);
    s = fmaf(a.z, a.z, s); s = fmaf(a.w, a.w, s);
    s = fmaf(b.x, b.x, s); s = fmaf(b.y, b.y, s);
    s = fmaf(b.z, b.z, s); s = fmaf(b.w, b.w, s);
#pragma unroll
    for (int o = 16; o; o >>= 1) s += __shfl_xor_sync(0xffffffffu, s, o);
    if (lane == 0) g_zsq[row] = s;
}
__global__ void prep_e_kernel(const float* __restrict__ e) {
    if (blockIdx.x == 0 && threadIdx.x == 0) g_loss = 0.0;
    int row  = blockIdx.x * 8 + (threadIdx.x >> 5);
    int lane = threadIdx.x & 31;
    const float4* er = (const float4*)(e + (size_t)row * D_DIM);
    float4 a = er[lane * 2], b = er[lane * 2 + 1];
    __nv_bfloat162 p0 = __floats2bfloat162_rn(a.x, a.y);
    __nv_bfloat162 p1 = __floats2bfloat162_rn(a.z, a.w);
    __nv_bfloat162 p2 = __floats2bfloat162_rn(b.x, b.y);
    __nv_bfloat162 p3 = __floats2bfloat162_rn(b.z, b.w);
    uint4 u;
    u.x = *(uint32_t*)&p0; u.y = *(uint32_t*)&p1;
    u.z = *(uint32_t*)&p2; u.w = *(uint32_t*)&p3;
    *(uint4*)(g_Eh + (size_t)row * D_DIM + lane * 8) = u;
    float s = 0.f;
    s = fmaf(a.x, a.x, s); s = fmaf(a.y, a.y, s);
    s = fmaf(a.z, a.z, s); s = fmaf(a.w, a.w, s);
    s = fmaf(b.x, b.x, s); s = fmaf(b.y, b.y, s);
    s = fmaf(b.z, b.z, s); s = fmaf(b.w, b.w, s);
#pragma unroll
    for (int o = 16; o; o >>= 1) s += __shfl_xor_sync(0xffffffffu, s, o);
    if (lane == 0) g_esq[row] = s;
}

// ---------------- main kernel ----------------
__global__ __launch_bounds__(NTHREADS, 2) void vq_main_kernel(
    const float* __restrict__ Z, const float* __restrict__ E,
    float* __restrict__ out) {

    extern __shared__ char smem[];
    const uint32_t sb = smem_u32(smem);
    const int t      = threadIdx.x;
    const int wid    = t >> 5;
    const int lane   = t & 31;
    const int warp_m = wid >> 2;   // 0..1
    const int warp_n = wid & 3;    // 0..3
    const int m0     = blockIdx.x * BM;

    int*   runm_i = (int*)(smem + OFF_RUNM);
    int*   idx_s  = (int*)(smem + OFF_IDX);
    int*   cnt_s  = (int*)(smem + OFF_CNT);
    float* wsum   = (float*)(smem + OFF_WSUM);
    float* esqc   = (float*)(smem + OFF_ESQC);
    int*   cand   = (int*)(smem + OFF_CAND);

    // resident A (Zh): 4096 uint4, swizzled 16B chunks (32 per 512B row)
    const uint4* Zh4 = (const uint4*)g_Zh;
    for (int i = t; i < 4096; i += NTHREADS) {
        int row = i >> 5, ch = i & 31;
        uint4 v = Zh4[(size_t)(m0 + row) * 32 + ch];
        *(uint4*)(smem + OFF_A + row * 512 + ((ch ^ (row & 7)) * 16)) = v;
    }
    if (t < BM) { runm_i[t] = 0x7F7FFFFF; cnt_s[t] = 0; }

    float zsv[4][2];
#pragma unroll
    for (int mi = 0; mi < 4; mi++)
#pragma unroll
        for (int h = 0; h < 2; h++)
            zsv[mi][h] = g_zsq[m0 + warp_m * 64 + mi * 16 + (lane >> 2) + 8 * h];

    const uint4* Eh4 = (const uint4*)g_Eh;

    // prologue: async-copy slice 0 of chunk 0 into buf0
    {
        int row = t >> 1, ch4 = (t & 1) * 4;
#pragma unroll
        for (int j = 0; j < 4; j++) {
            int ch = ch4 + j;
            cp16(sb + OFF_B + row * 128 + ((ch ^ (row & 7)) * 16),
                 Eh4 + (size_t)row * 32 + ch);
        }
        cp_commit();
    }

    float c[4][4][4];

    for (int g = 0; g < NITER; g++) {
        cp_wait0();
        __syncthreads();
        const int cidx = g >> 2;
        const int s    = g & 3;

        if (s == 0) {
#pragma unroll
            for (int mi = 0; mi < 4; mi++)
#pragma unroll
                for (int ni = 0; ni < 4; ni++)
#pragma unroll
                    for (int q = 0; q < 4; q++) c[mi][ni][q] = 0.f;
            if (t < BN) esqc[t] = g_esq[cidx * BN + t];
        }

        // prefetch next slice into the other buffer
        if (g < NITER - 1) {
            int gn = g + 1, cn = gn >> 2, sn = gn & 3;
            int row = t >> 1, ch4 = (t & 1) * 4;
            uint32_t dbase = sb + OFF_B + (gn & 1) * 16384;
#pragma unroll
            for (int j = 0; j < 4; j++) {
                int ch = ch4 + j;
                cp16(dbase + row * 128 + ((ch ^ (row & 7)) * 16),
                     Eh4 + (size_t)(cn * BN + row) * 32 + sn * 8 + ch);
            }
            cp_commit();
        }

        const uint32_t bb = sb + OFF_B + (g & 1) * 16384;
#pragma unroll
        for (int tk = 0; tk < 4; tk++) {
            const int kg = s * 4 + tk;
            uint32_t ah[4][4];
#pragma unroll
            for (int mi = 0; mi < 4; mi++) {
                int row = warp_m * 64 + mi * 16 + (lane & 15);
                int ch  = kg * 2 + (lane >> 4);
                uint32_t adr = sb + OFF_A + row * 512 + ((ch ^ (row & 7)) * 16);
                ldsm_x4(ah[mi][0], ah[mi][1], ah[mi][2], ah[mi][3], adr);
            }
            uint32_t bh[4][2];
#pragma unroll
            for (int ni = 0; ni < 4; ni++) {
                int rn = warp_n * 32 + ni * 8 + (lane & 7);
                int ch = tk * 2 + ((lane >> 3) & 1);
                uint32_t adr = bb + rn * 128 + ((ch ^ (rn & 7)) * 16);
                ldsm_x2(bh[ni][0], bh[ni][1], adr);
            }
#pragma unroll
            for (int mi = 0; mi < 4; mi++)
#pragma unroll
                for (int ni = 0; ni < 4; ni++)
                    mma16816(c[mi][ni], ah[mi], bh[ni]);
        }

        if (s == 3) {
            const int n0 = cidx * BN;
            if (cidx == 0) {
                // establish runm before any collection (else thr = +inf)
#pragma unroll
                for (int mi = 0; mi < 4; mi++)
#pragma unroll
                    for (int h = 0; h < 2; h++) {
                        float v = 3.4e38f;
#pragma unroll
                        for (int ni = 0; ni < 4; ni++)
#pragma unroll
                            for (int jc = 0; jc < 2; jc++) {
                                int nl = warp_n * 32 + ni * 8 + (lane & 3) * 2 + jc;
                                float d = fmaf(-2.0f, c[mi][ni][h * 2 + jc],
                                               zsv[mi][h] + esqc[nl]);
                                v = fminf(v, d);
                            }
#pragma unroll
                        for (int off = 1; off <= 2; off <<= 1)
                            v = fminf(v, __shfl_xor_sync(0xffffffffu, v, off));
                        if ((lane & 3) == 0) {
                            int rl = warp_m * 64 + mi * 16 + (lane >> 2) + 8 * h;
                            atomicMin(&runm_i[rl], __float_as_int(v));
                        }
                    }
                __syncthreads();
            }
            // single-pass collect vs (possibly stale) running min; then update
#pragma unroll
            for (int mi = 0; mi < 4; mi++)
#pragma unroll
                for (int h = 0; h < 2; h++) {
                    int rl = warp_m * 64 + mi * 16 + (lane >> 2) + 8 * h;
                    float thr = __int_as_float(runm_i[rl]) + MARGIN;
                    float v = 3.4e38f;
#pragma unroll
                    for (int ni = 0; ni < 4; ni++)
#pragma unroll
                        for (int jc = 0; jc < 2; jc++) {
                            int nl = warp_n * 32 + ni * 8 + (lane & 3) * 2 + jc;
                            float d = fmaf(-2.0f, c[mi][ni][h * 2 + jc],
                                           zsv[mi][h] + esqc[nl]);
                            v = fminf(v, d);
                            if (d <= thr) {
                                int pos = atomicAdd(&cnt_s[rl], 1);
                                if (pos < MAXC) cand[rl * MAXC + pos] = n0 + nl;
                            }
                        }
                    if (cidx < NCHUNK - 1) {
#pragma unroll
                        for (int off = 1; off <= 2; off <<= 1)
                            v = fminf(v, __shfl_xor_sync(0xffffffffu, v, off));
                        if ((lane & 3) == 0)
                            atomicMin(&runm_i[rl], __float_as_int(v));
                    }
                }
        }
    }
    __syncthreads();

    // ---- exact fp32 refinement: one warp per 16 rows ----
    for (int rr = 0; rr < BM / 8; rr++) {
        int r = wid * (BM / 8) + rr;
        const float* zrow = Z + (size_t)(m0 + r) * D_DIM;
        float zreg[8];
#pragma unroll
        for (int j = 0; j < 8; j++) zreg[j] = zrow[lane + 32 * j];
        float zs = g_zsq[m0 + r];
        int cnt = cnt_s[r];
        float bv = 3.4e38f;
        int   bi = 0x7fffffff;
        if (cnt <= MAXC) {
            for (int ci = 0; ci < cnt; ci++) {
                int n = cand[r * MAXC + ci];
                const float* erow = E + (size_t)n * D_DIM;
                float p = 0.f;
#pragma unroll
                for (int j = 0; j < 8; j++) p = fmaf(zreg[j], erow[lane + 32 * j], p);
#pragma unroll
                for (int o = 16; o; o >>= 1) p += __shfl_xor_sync(0xffffffffu, p, o);
                float d = fmaf(-2.0f, p, zs + g_esq[n]);
                if (d < bv || (d == bv && n < bi)) { bv = d; bi = n; }
            }
        } else {
            // overflow fallback: exact scan of all codes (effectively never)
            for (int n = 0; n < K_CODES; n++) {
                const float* erow = E + (size_t)n * D_DIM;
                float p = 0.f;
#pragma unroll
                for (int j = 0; j < 8; j++) p = fmaf(zreg[j], erow[lane + 32 * j], p);
#pragma unroll
                for (int o = 16; o; o >>= 1) p += __shfl_xor_sync(0xffffffffu, p, o);
                float d = fmaf(-2.0f, p, zs + g_esq[n]);
                if (d < bv) { bv = d; bi = n; }
            }
        }
        if (lane == 0) {
            idx_s[r] = bi;
            out[(size_t)M_ROWS * D_DIM + 1 + m0 + r] = (float)bi;
        }
    }
    __syncthreads();

    // ---- gather z_q + loss partial (exact fp32 from originals) ----
    const float4* Zf4 = (const float4*)Z;
    const float4* Ef4 = (const float4*)E;
    float4* Of4 = (float4*)out;
    float part = 0.f;
    for (int i = t; i < BM * (D_DIM / 4); i += NTHREADS) {
        int m = i >> 6, cidx2 = i & 63;
        int bi = idx_s[m];
        float4 e = Ef4[(size_t)bi * (D_DIM / 4) + cidx2];
        float4 z = Zf4[(size_t)(m0 + m) * (D_DIM / 4) + cidx2];
        Of4[(size_t)(m0 + m) * (D_DIM / 4) + cidx2] = e;
        float dx = e.x - z.x, dy = e.y - z.y, dz = e.z - z.z, dw = e.w - z.w;
        part = fmaf(dx, dx, part); part = fmaf(dy, dy, part);
        part = fmaf(dz, dz, part); part = fmaf(dw, dw, part);
    }
#pragma unroll
    for (int o = 16; o; o >>= 1) part += __shfl_xor_sync(0xffffffffu, part, o);
    if (lane == 0) wsum[wid] = part;
    __syncthreads();
    if (t == 0) {
        float s = 0.f;
#pragma unroll
        for (int w = 0; w < NTHREADS / 32; w++) s += wsum[w];
        atomicAdd(&g_loss, (double)s);
    }
}

__global__ void finalize_kernel(float* __restrict__ out) {
    out[(size_t)M_ROWS * D_DIM] =
        (float)(1.25 * g_loss / ((double)M_ROWS * (double)D_DIM));
}

// ---------------------------------------------------------------------------
extern "C" void kernel_launch(void* const* d_in, const int* in_sizes, int n_in,
                              void* d_out, int out_size) {
    (void)in_sizes; (void)n_in; (void)out_size;
    const float* z = (const float*)d_in[0];
    const float* e = (const float*)d_in[1];
    float* out = (float*)d_out;

    cudaFuncSetAttribute(vq_main_kernel,
                         cudaFuncAttributeMaxDynamicSharedMemorySize, SMEM_BYTES);

    prep_z_kernel<<<M_ROWS / 8, 256>>>(z);
    prep_e_kernel<<<K_CODES / 8, 256>>>(e);
    vq_main_kernel<<<M_ROWS / BM, NTHREADS, SMEM_BYTES>>>(z, e, out);
    finalize_kernel<<<1, 1>>>(out);
}

// round 16
// speedup vs baseline: 1.9073x; 1.9073x over previous
#include <cuda_runtime.h>
#include <cuda_bf16.h>
#include <cstdint>

// VQ-VAE quantizer — 1-term bf16 HMMA approx distances + exact fp32 refinement.
// R15 = R6 mainloop byte-identical + fused prep kernels + in-kernel finalize.

#define M_ROWS  65536
#define K_CODES 2048
#define D_DIM   256
#define BM      128
#define BN      128
#define NCHUNK  (K_CODES / BN)   // 16
#define NTHREADS 256
#define MAXC    16
#define MARGIN  6e-4f

// smem layout (dynamic) — identical to R6
#define OFF_REDV  0        // [4][128] float = 2048
#define OFF_RUNM  2048     // 128 float
#define OFF_IDX   2560     // 128 int
#define OFF_CNT   3072     // 128 int
#define OFF_WSUM  3584     // 8 float
#define OFF_CAND  4096     // 128*16 int = 8192
#define OFF_A     12288    // Zh tile 64KB -> ends 77824
#define OFF_B     77824    // 2 x 16KB -> ends 110592
#define SMEM_BYTES 110592

__device__ float  g_zsq[M_ROWS];
__device__ float  g_esq[K_CODES];
__device__ double g_loss;
__device__ unsigned int g_ctr;
__device__ __nv_bfloat16 g_Zh[(size_t)M_ROWS * D_DIM];
__device__ __nv_bfloat16 g_Eh[(size_t)K_CODES * D_DIM];

__device__ __forceinline__ uint32_t smem_u32(const void* p) {
    uint32_t a;
    asm("{ .reg .u64 t; cvta.to.shared.u64 t, %1; cvt.u32.u64 %0, t; }" : "=r"(a) : "l"(p));
    return a;
}
__device__ __forceinline__ void ldsm_x4(uint32_t& r0, uint32_t& r1, uint32_t& r2,
                                        uint32_t& r3, uint32_t addr) {
    asm volatile("ldmatrix.sync.aligned.m8n8.x4.shared.b16 {%0,%1,%2,%3}, [%4];"
                 : "=r"(r0), "=r"(r1), "=r"(r2), "=r"(r3) : "r"(addr));
}
__device__ __forceinline__ void ldsm_x2(uint32_t& r0, uint32_t& r1, uint32_t addr) {
    asm volatile("ldmatrix.sync.aligned.m8n8.x2.shared.b16 {%0,%1}, [%2];"
                 : "=r"(r0), "=r"(r1) : "r"(addr));
}
__device__ __forceinline__ void mma16816(float* c, const uint32_t* a, const uint32_t* b) {
    asm volatile("mma.sync.aligned.m16n8k16.row.col.f32.bf16.bf16.f32 "
                 "{%0,%1,%2,%3}, {%4,%5,%6,%7}, {%8,%9}, {%0,%1,%2,%3};"
                 : "+f"(c[0]), "+f"(c[1]), "+f"(c[2]), "+f"(c[3])
                 : "r"(a[0]), "r"(a[1]), "r"(a[2]), "r"(a[3]), "r"(b[0]), "r"(b[1]));
}

// ---------------- fused prep: convert to bf16 + row sum-of-squares ----------
__global__ void prep_z_kernel(const float* __restrict__ z) {
    int row  = blockIdx.x * 8 + (threadIdx.x >> 5);
    int lane = threadIdx.x & 31;
    const float4* zr = (const float4*)(z + (size_t)row * D_DIM);
    float4 a = zr[lane * 2], b = zr[lane * 2 + 1];
    __nv_bfloat162 p0 = __floats2bfloat162_rn(a.x, a.y);
    __nv_bfloat162 p1 = __floats2bfloat162_rn(a.z, a.w);
    __nv_bfloat162 p2 = __floats2bfloat162_rn(b.x, b.y);
    __nv_bfloat162 p3 = __floats2bfloat162_rn(b.z, b.w);
    uint4 u;
    u.x = *(uint32_t*)&p0; u.y = *(uint32_t*)&p1;
    u.z = *(uint32_t*)&p2; u.w = *(uint32_t*)&p3;
    *(uint4*)(g_Zh + (size_t)row * D_DIM + lane * 8) = u;
    float s = 0.f;
    s = fmaf(a.x, a.x, s); s = fmaf(a.y, a.y, s);
    s = fmaf(a.z, a.z, s); s = fmaf(a.w, a.w, s);
    s = fmaf(b.x, b.x, s); s = fmaf(b.y, b.y, s);
    s = fmaf(b.z, b.z, s); s = fmaf(b.w, b.w, s);
#pragma unroll
    for (int o = 16; o; o >>= 1) s += __shfl_xor_sync(0xffffffffu, s, o);
    if (lane == 0) g_zsq[row] = s;
}
__global__ void prep_e_kernel(const float* __restrict__ e) {
    if (blockIdx.x == 0 && threadIdx.x == 0) { g_loss = 0.0; g_ctr = 0u; }
    int row  = blockIdx.x * 8 + (threadIdx.x >> 5);
    int lane = threadIdx.x & 31;
    const float4* er = (const float4*)(e + (size_t)row * D_DIM);
    float4 a = er[lane * 2], b = er[lane * 2 + 1];
    __nv_bfloat162 p0 = __floats2bfloat162_rn(a.x, a.y);
    __nv_bfloat162 p1 = __floats2bfloat162_rn(a.z, a.w);
    __nv_bfloat162 p2 = __floats2bfloat162_rn(b.x, b.y);
    __nv_bfloat162 p3 = __floats2bfloat162_rn(b.z, b.w);
    uint4 u;
    u.x = *(uint32_t*)&p0; u.y = *(uint32_t*)&p1;
    u.z = *(uint32_t*)&p2; u.w = *(uint32_t*)&p3;
    *(uint4*)(g_Eh + (size_t)row * D_DIM + lane * 8) = u;
    float s = 0.f;
    s = fmaf(a.x, a.x, s); s = fmaf(a.y, a.y, s);
    s = fmaf(a.z, a.z, s); s = fmaf(a.w, a.w, s);
    s = fmaf(b.x, b.x, s); s = fmaf(b.y, b.y, s);
    s = fmaf(b.z, b.z, s); s = fmaf(b.w, b.w, s);
#pragma unroll
    for (int o = 16; o; o >>= 1) s += __shfl_xor_sync(0xffffffffu, s, o);
    if (lane == 0) g_esq[row] = s;
}

// ---------------- main kernel (R6 structure, byte-identical mainloop) -------
__global__ __launch_bounds__(NTHREADS, 2) void vq_main_kernel(
    const float* __restrict__ Z, const float* __restrict__ E,
    float* __restrict__ out) {

    extern __shared__ char smem[];
    const uint32_t sb = smem_u32(smem);
    const int t      = threadIdx.x;
    const int wid    = t >> 5;
    const int lane   = t & 31;
    const int warp_m = wid >> 2;   // 0..1
    const int warp_n = wid & 3;    // 0..3
    const int m0     = blockIdx.x * BM;

    float* red_v  = (float*)(smem + OFF_REDV);
    float* runm   = (float*)(smem + OFF_RUNM);
    int*   idx_s  = (int*)(smem + OFF_IDX);
    int*   cnt_s  = (int*)(smem + OFF_CNT);
    float* wsum   = (float*)(smem + OFF_WSUM);
    int*   cand   = (int*)(smem + OFF_CAND);

    // resident A (Zh): 4096 uint4, swizzled 16B chunks (32 per 512B row)
    const uint4* Zh4 = (const uint4*)g_Zh;
    for (int i = t; i < 4096; i += NTHREADS) {
        int row = i >> 5, ch = i & 31;
        uint4 v = Zh4[(size_t)(m0 + row) * 32 + ch];
        *(uint4*)(smem + OFF_A + row * 512 + ((ch ^ (row & 7)) * 16)) = v;
    }
    if (t < BM) { runm[t] = 3.4e38f; cnt_s[t] = 0; }

    float zsv[4][2];
#pragma unroll
    for (int mi = 0; mi < 4; mi++)
#pragma unroll
        for (int h = 0; h < 2; h++)
            zsv[mi][h] = g_zsq[m0 + warp_m * 64 + mi * 16 + (lane >> 2) + 8 * h];

    __syncthreads();

    float bestv = 3.4e38f;
    int   besti = 0;

    const uint4* Eh4 = (const uint4*)g_Eh;

    for (int nt = 0; nt < NCHUNK; nt++) {
        const int n0 = nt * BN;

        float c[4][4][4];
#pragma unroll
        for (int mi = 0; mi < 4; mi++)
#pragma unroll
            for (int ni = 0; ni < 4; ni++)
#pragma unroll
                for (int q = 0; q < 4; q++) c[mi][ni][q] = 0.f;

        // stage slice 0 into buf0 (Bh only: 1024 uint4)
#pragma unroll
        for (int j = 0; j < 4; j++) {
            int i = t + j * NTHREADS;
            int row = i >> 3, ch = i & 7;
            uint4 v = Eh4[(size_t)(n0 + row) * 32 + ch];
            *(uint4*)(smem + OFF_B + row * 128 + ((ch ^ (row & 7)) * 16)) = v;
        }
        __syncthreads();

#pragma unroll 1
        for (int s = 0; s < 4; s++) {
            uint4 nx[4];
            if (s < 3) {
#pragma unroll
                for (int j = 0; j < 4; j++) {
                    int i = t + j * NTHREADS;
                    int row = i >> 3, ch = i & 7;
                    nx[j] = Eh4[(size_t)(n0 + row) * 32 + (s + 1) * 8 + ch];
                }
            }
            const uint32_t bb = sb + OFF_B + (s & 1) * 16384;
#pragma unroll
            for (int tk = 0; tk < 4; tk++) {
                const int kg = s * 4 + tk;
                uint32_t ah[4][4];
#pragma unroll
                for (int mi = 0; mi < 4; mi++) {
                    int row = warp_m * 64 + mi * 16 + (lane & 15);
                    int ch  = kg * 2 + (lane >> 4);
                    uint32_t adr = sb + OFF_A + row * 512 + ((ch ^ (row & 7)) * 16);
                    ldsm_x4(ah[mi][0], ah[mi][1], ah[mi][2], ah[mi][3], adr);
                }
                uint32_t bh[4][2];
#pragma unroll
                for (int ni = 0; ni < 4; ni++) {
                    int rn = warp_n * 32 + ni * 8 + (lane & 7);
                    int ch = tk * 2 + ((lane >> 3) & 1);
                    uint32_t adr = bb + rn * 128 + ((ch ^ (rn & 7)) * 16);
                    ldsm_x2(bh[ni][0], bh[ni][1], adr);
                }
#pragma unroll
                for (int mi = 0; mi < 4; mi++)
#pragma unroll
                    for (int ni = 0; ni < 4; ni++)
                        mma16816(c[mi][ni], ah[mi], bh[ni]);
            }
            if (s < 3) {
#pragma unroll
                for (int j = 0; j < 4; j++) {
                    int i = t + j * NTHREADS;
                    int row = i >> 3, ch = i & 7;
                    *(uint4*)(smem + OFF_B + ((s + 1) & 1) * 16384 +
                              row * 128 + ((ch ^ (row & 7)) * 16)) = nx[j];
                }
            }
            __syncthreads();
        }

        // ---- pass A: chunk-local per-row min of d_hat ----
#pragma unroll
        for (int mi = 0; mi < 4; mi++)
#pragma unroll
            for (int h = 0; h < 2; h++) {
                float v = 3.4e38f;
#pragma unroll
                for (int ni = 0; ni < 4; ni++)
#pragma unroll
                    for (int jc = 0; jc < 2; jc++) {
                        int n = n0 + warp_n * 32 + ni * 8 + (lane & 3) * 2 + jc;
                        float d = fmaf(-2.0f, c[mi][ni][h * 2 + jc], zsv[mi][h] + g_esq[n]);
                        v = fminf(v, d);
                    }
#pragma unroll
                for (int off = 1; off <= 2; off <<= 1)
                    v = fminf(v, __shfl_xor_sync(0xffffffffu, v, off));
                if ((lane & 3) == 0) {
                    int rl = warp_m * 64 + mi * 16 + (lane >> 2) + 8 * h;
                    red_v[warp_n * 128 + rl] = v;
                }
            }
        __syncthreads();
        if (t < BM) {
            float v = red_v[t];
#pragma unroll
            for (int w = 1; w < 4; w++) v = fminf(v, red_v[w * 128 + t]);
            runm[t] = fminf(runm[t], v);
        }
        __syncthreads();

        // ---- pass B: collect candidates within margin of running min ----
#pragma unroll
        for (int mi = 0; mi < 4; mi++)
#pragma unroll
            for (int h = 0; h < 2; h++) {
                int rl = warp_m * 64 + mi * 16 + (lane >> 2) + 8 * h;
                float thr = runm[rl] + MARGIN;
#pragma unroll
                for (int ni = 0; ni < 4; ni++)
#pragma unroll
                    for (int jc = 0; jc < 2; jc++) {
                        int n = n0 + warp_n * 32 + ni * 8 + (lane & 3) * 2 + jc;
                        float d = fmaf(-2.0f, c[mi][ni][h * 2 + jc], zsv[mi][h] + g_esq[n]);
                        if (d <= thr) {
                            int pos = atomicAdd(&cnt_s[rl], 1);
                            if (pos < MAXC) cand[rl * MAXC + pos] = n;
                        }
                    }
            }
        __syncthreads();
    }

    if (t < BM) { (void)bestv; (void)besti; }

    // ---- exact fp32 refinement: one warp per 16 rows ----
    for (int rr = 0; rr < BM / 8; rr++) {
        int r = wid * (BM / 8) + rr;
        const float* zrow = Z + (size_t)(m0 + r) * D_DIM;
        float zreg[8];
#pragma unroll
        for (int j = 0; j < 8; j++) zreg[j] = zrow[lane + 32 * j];
        float zs = g_zsq[m0 + r];
        int cnt = cnt_s[r];
        float bv = 3.4e38f;
        int   bi = 0x7fffffff;
        if (cnt <= MAXC) {
            for (int ci = 0; ci < cnt; ci++) {
                int n = cand[r * MAXC + ci];
                const float* erow = E + (size_t)n * D_DIM;
                float p = 0.f;
#pragma unroll
                for (int j = 0; j < 8; j++) p = fmaf(zreg[j], erow[lane + 32 * j], p);
#pragma unroll
                for (int o = 16; o; o >>= 1) p += __shfl_xor_sync(0xffffffffu, p, o);
                float d = fmaf(-2.0f, p, zs + g_esq[n]);
                if (d < bv || (d == bv && n < bi)) { bv = d; bi = n; }
            }
        } else {
            // overflow fallback: exact scan of all codes (effectively never)
            for (int n = 0; n < K_CODES; n++) {
                const float* erow = E + (size_t)n * D_DIM;
                float p = 0.f;
#pragma unroll
                for (int j = 0; j < 8; j++) p = fmaf(zreg[j], erow[lane + 32 * j], p);
#pragma unroll
                for (int o = 16; o; o >>= 1) p += __shfl_xor_sync(0xffffffffu, p, o);
                float d = fmaf(-2.0f, p, zs + g_esq[n]);
                if (d < bv) { bv = d; bi = n; }
            }
        }
        if (lane == 0) {
            idx_s[r] = bi;
            out[(size_t)M_ROWS * D_DIM + 1 + m0 + r] = (float)bi;
        }
    }
    __syncthreads();

    // ---- gather z_q + loss partial (exact fp32 from originals) ----
    const float4* Zf4 = (const float4*)Z;
    const float4* Ef4 = (const float4*)E;
    float4* Of4 = (float4*)out;
    float part = 0.f;
    for (int i = t; i < BM * (D_DIM / 4); i += NTHREADS) {
        int m = i >> 6, cidx = i & 63;
        int bi = idx_s[m];
        float4 e = Ef4[(size_t)bi * (D_DIM / 4) + cidx];
        float4 z = Zf4[(size_t)(m0 + m) * (D_DIM / 4) + cidx];
        Of4[(size_t)(m0 + m) * (D_DIM / 4) + cidx] = e;
        float dx = e.x - z.x, dy = e.y - z.y, dz = e.z - z.z, dw = e.w - z.w;
        part = fmaf(dx, dx, part); part = fmaf(dy, dy, part);
        part = fmaf(dz, dz, part); part = fmaf(dw, dw, part);
    }
#pragma unroll
    for (int o = 16; o; o >>= 1) part += __shfl_xor_sync(0xffffffffu, part, o);
    if (lane == 0) wsum[wid] = part;
    __syncthreads();
    if (t == 0) {
        float s = 0.f;
#pragma unroll
        for (int w = 0; w < NTHREADS / 32; w++) s += wsum[w];
        double old = atomicAdd(&g_loss, (double)s);
        (void)old;
        __threadfence();
        unsigned int done = atomicAdd(&g_ctr, 1u);
        if (done == (unsigned int)(gridDim.x - 1)) {
            // all CTAs' loss partials are globally visible (each fenced
            // before incrementing the counter). Read-modify-write with 0
            // returns the full sum.
            double total = atomicAdd(&g_loss, 0.0);
            out[(size_t)M_ROWS * D_DIM] =
                (float)(1.25 * total / ((double)M_ROWS * (double)D_DIM));
        }
    }
}

// ---------------------------------------------------------------------------
extern "C" void kernel_launch(void* const* d_in, const int* in_sizes, int n_in,
                              void* d_out, int out_size) {
    (void)in_sizes; (void)n_in; (void)out_size;
    const float* z = (const float*)d_in[0];
    const float* e = (const float*)d_in[1];
    float* out = (float*)d_out;

    cudaFuncSetAttribute(vq_main_kernel,
                         cudaFuncAttributeMaxDynamicSharedMemorySize, SMEM_BYTES);

    prep_z_kernel<<<M_ROWS / 8, 256>>>(z);
    prep_e_kernel<<<K_CODES / 8, 256>>>(e);
    vq_main_kernel<<<M_ROWS / BM, NTHREADS, SMEM_BYTES>>>(z, e, out);
}